// round 10
// baseline (speedup 1.0000x reference)
#include <cuda_runtime.h>
#include <cuda_bf16.h>

#define N_NEURON 128
#define N_RULES  512
#define BATCH    4096

// One warp per batch element b; 4 neuron rows (16 x LDG.128) front-batched
// per iteration to deepen per-warp memory-level parallelism.
// No min-blocks clamp: let ptxas take ~90-110 regs (no spills) at ~4-5 CTAs/SM.
__global__ void __launch_bounds__(128) lei_fused_kernel(
    const float* __restrict__ x,
    const float* __restrict__ head_w,
    const float* __restrict__ head_b,
    const float* __restrict__ foot_w,
    const float* __restrict__ foot_b,
    float* __restrict__ out)
{
    const int warp = threadIdx.x >> 5;
    const int lane = threadIdx.x & 31;
    const int b = blockIdx.x * 4 + warp;   // 1024 blocks * 4 warps = 4096

    const float* __restrict__ fw0 = foot_w;            // [128]
    const float* __restrict__ fw1 = foot_w + N_NEURON; // [128]

    float acc0 = 0.0f, acc1 = 0.0f;

    // Fold the head bias contribution: sum_n head_b[n]*fw_j[n], split across lanes.
#pragma unroll
    for (int k = 0; k < 4; k++) {
        int n = 32 * k + lane;
        float hb = head_b[n];
        acc0 = fmaf(hb, fw0[n], acc0);
        acc1 = fmaf(hb, fw1[n], acc1);
    }

    const float4* __restrict__ xb =
        reinterpret_cast<const float4*>(x) + (size_t)b * (N_RULES / 4);
    const size_t nstride = (size_t)BATCH * (N_RULES / 4);  // float4 stride between neurons
    const float4* __restrict__ wq = reinterpret_cast<const float4*>(head_w);

    for (int n = 0; n < N_NEURON; n += 4) {
        // Front-batch 16 x loads (4 neurons' rows) for deep MLP.
        float4 xv[16];
#pragma unroll
        for (int r = 0; r < 4; r++) {
            const float4* p = xb + (size_t)(n + r) * nstride;
#pragma unroll
            for (int k = 0; k < 4; k++)
                xv[4 * r + k] = p[lane + 32 * k];
        }

        float pr[4];
#pragma unroll
        for (int r = 0; r < 4; r++) {
            float pa = 0.0f;
            const float4* w = wq + (size_t)(n + r) * (N_RULES / 4);
#pragma unroll
            for (int k = 0; k < 4; k++) {
                float4 wv = w[lane + 32 * k];
                pa = fmaf(xv[4 * r + k].x, wv.x, pa);
                pa = fmaf(xv[4 * r + k].y, wv.y, pa);
                pa = fmaf(xv[4 * r + k].z, wv.z, pa);
                pa = fmaf(xv[4 * r + k].w, wv.w, pa);
            }
            pr[r] = pa;
        }

#pragma unroll
        for (int r = 0; r < 4; r++) {
            acc0 = fmaf(pr[r], fw0[n + r], acc0);
            acc1 = fmaf(pr[r], fw1[n + r], acc1);
        }
    }

    // Warp reduction of the two logit accumulators.
#pragma unroll
    for (int off = 16; off; off >>= 1) {
        acc0 += __shfl_xor_sync(0xFFFFFFFFu, acc0, off);
        acc1 += __shfl_xor_sync(0xFFFFFFFFu, acc1, off);
    }

    if (lane == 0) {
        float l0 = acc0 + foot_b[0];
        float l1 = acc1 + foot_b[1];
        float m  = fmaxf(l0, l1);
        float e0 = __expf(l0 - m);
        float e1 = __expf(l1 - m);
        float inv = 1.0f / (e0 + e1);
        out[b * 2 + 0] = e0 * inv;
        out[b * 2 + 1] = e1 * inv;
    }
}

extern "C" void kernel_launch(void* const* d_in, const int* in_sizes, int n_in,
                              void* d_out, int out_size)
{
    const float* x      = (const float*)d_in[0];
    const float* head_w = (const float*)d_in[1];
    const float* head_b = (const float*)d_in[2];
    const float* foot_w = (const float*)d_in[3];
    const float* foot_b = (const float*)d_in[4];
    float* out = (float*)d_out;

    // 4096 warps total, one per batch element: 1024 blocks x 128 threads.
    lei_fused_kernel<<<BATCH / 4, 128>>>(x, head_w, head_b, foot_w, foot_b, out);
}

// round 13
// speedup vs baseline: 1.2011x; 1.2011x over previous
#include <cuda_runtime.h>
#include <cuda_bf16.h>

#define N_NEURON 128
#define N_RULES  512
#define BATCH    4096

// FINAL (converged R2 configuration, best measured 155.68us):
// One warp per batch element b, fully fused:
//   logit_j[b] = sum_n foot_w[j,n]*( x[n,b,:].head_w[n,:] + head_b[n] ) + foot_b[j]
// then 2-way softmax. Per-lane weighted accumulators; one warp-reduce at the end.
//
// Load shape is the measured optimum:
//  - 8 front-batched LDG.128 per warp per iteration (2 neuron rows = 113 KB/SM in flight)
//  - __launch_bounds__(128, 8) is LOAD-BEARING: it makes ptxas allocate 64 regs and
//    keep the full 8-float4 batch live (without it ptxas drops to 40 regs,
//    interleaves loads with FMAs, MLP collapses, DRAM% falls 85 -> 72).
//  - head_w (256 KB) is cache-resident: measured DRAM bytes == sizeof(x) (1.0737 GB).
// Achieved 6.90 TB/s == B300 LTS chip-throughput cap (path-independent).
// Probed and rejected: split-n 2x warps (-7%), L2 prefetch (-15%), __ldcs (0),
// 16-deep batch via compiler (-19%). This is the hardware ceiling.
__global__ void __launch_bounds__(128, 8) lei_fused_kernel(
    const float* __restrict__ x,
    const float* __restrict__ head_w,
    const float* __restrict__ head_b,
    const float* __restrict__ foot_w,
    const float* __restrict__ foot_b,
    float* __restrict__ out)
{
    const int warp = threadIdx.x >> 5;
    const int lane = threadIdx.x & 31;
    const int b = blockIdx.x * 4 + warp;   // 1024 blocks * 4 warps = 4096

    const float* __restrict__ fw0 = foot_w;            // [128]
    const float* __restrict__ fw1 = foot_w + N_NEURON; // [128]

    float acc0 = 0.0f, acc1 = 0.0f;

    // Fold the head bias contribution: sum_n head_b[n]*fw_j[n], split across lanes.
#pragma unroll
    for (int k = 0; k < 4; k++) {
        int n = 32 * k + lane;
        float hb = head_b[n];
        acc0 = fmaf(hb, fw0[n], acc0);
        acc1 = fmaf(hb, fw1[n], acc1);
    }

    const float4* __restrict__ xb =
        reinterpret_cast<const float4*>(x) + (size_t)b * (N_RULES / 4);
    const size_t nstride = (size_t)BATCH * (N_RULES / 4);  // float4 stride between neurons
    const float4* __restrict__ wq = reinterpret_cast<const float4*>(head_w);

    for (int n = 0; n < N_NEURON; n += 2) {
        // Front-batch 8 x loads (2 neurons' rows) for MLP.
        const float4* p0 = xb + (size_t)n * nstride;
        const float4* p1 = p0 + nstride;
        float4 xv[8];
#pragma unroll
        for (int k = 0; k < 4; k++) xv[k] = p0[lane + 32 * k];
#pragma unroll
        for (int k = 0; k < 4; k++) xv[4 + k] = p1[lane + 32 * k];

        float pa = 0.0f, pb = 0.0f;
#pragma unroll
        for (int k = 0; k < 4; k++) {
            float4 wv = wq[(size_t)n * (N_RULES / 4) + lane + 32 * k];
            pa = fmaf(xv[k].x, wv.x, pa);
            pa = fmaf(xv[k].y, wv.y, pa);
            pa = fmaf(xv[k].z, wv.z, pa);
            pa = fmaf(xv[k].w, wv.w, pa);
        }
#pragma unroll
        for (int k = 0; k < 4; k++) {
            float4 wv = wq[(size_t)(n + 1) * (N_RULES / 4) + lane + 32 * k];
            pb = fmaf(xv[4 + k].x, wv.x, pb);
            pb = fmaf(xv[4 + k].y, wv.y, pb);
            pb = fmaf(xv[4 + k].z, wv.z, pb);
            pb = fmaf(xv[4 + k].w, wv.w, pb);
        }

        acc0 = fmaf(pa, fw0[n], acc0);
        acc1 = fmaf(pa, fw1[n], acc1);
        acc0 = fmaf(pb, fw0[n + 1], acc0);
        acc1 = fmaf(pb, fw1[n + 1], acc1);
    }

    // Warp reduction of the two logit accumulators.
#pragma unroll
    for (int off = 16; off; off >>= 1) {
        acc0 += __shfl_xor_sync(0xFFFFFFFFu, acc0, off);
        acc1 += __shfl_xor_sync(0xFFFFFFFFu, acc1, off);
    }

    if (lane == 0) {
        float l0 = acc0 + foot_b[0];
        float l1 = acc1 + foot_b[1];
        float m  = fmaxf(l0, l1);
        float e0 = __expf(l0 - m);
        float e1 = __expf(l1 - m);
        float inv = 1.0f / (e0 + e1);
        out[b * 2 + 0] = e0 * inv;
        out[b * 2 + 1] = e1 * inv;
    }
}

extern "C" void kernel_launch(void* const* d_in, const int* in_sizes, int n_in,
                              void* d_out, int out_size)
{
    const float* x      = (const float*)d_in[0];
    const float* head_w = (const float*)d_in[1];
    const float* head_b = (const float*)d_in[2];
    const float* foot_w = (const float*)d_in[3];
    const float* foot_b = (const float*)d_in[4];
    float* out = (float*)d_out;

    // 4096 warps total, one per batch element: 1024 blocks x 128 threads.
    lei_fused_kernel<<<BATCH / 4, 128>>>(x, head_w, head_b, foot_w, foot_b, out);
}